// round 1
// baseline (speedup 1.0000x reference)
#include <cuda_runtime.h>
#include <math.h>

#define NB 4
#define FH 480
#define FW 640
#define NPIX (FH*FW)
#define NSEM 16
#define C_OBS 20
#define VR 100
#define HZ 80
#define MC 480
#define NCELL (VR*VR)          // 10000
#define G0_PER_B (NCELL*HZ)    // 800000
#define AG_Z0 13
#define AG_NZ 12
#define GS_PER_B (NCELL*AG_NZ) // 120000

// Output layout: fp_map_pred (NB*NCELL) | map_pred (NB*20*480*480) | poses (12) | poses (12)
#define OUT_MAP_OFF ((size_t)NB*NCELL)
#define OUT_POSE_OFF (OUT_MAP_OFF + (size_t)NB*C_OBS*MC*MC)

// ---------- scratch (static device globals; no allocation allowed) ----------
__device__ __align__(16) float g_g0[NB*G0_PER_B];          // channel-0 voxel grid, [b][(x*100+y)*80+z]
__device__ __align__(16) float g_gs[NB*GS_PER_B*16];       // sem voxels, [b][(x*100+y)*12+(z-13)][16]
__device__ float g_pm0[NB*NCELL];                          // clip(agent0)   [b][y*100+x]
__device__ float g_pe0[NB*NCELL];                          // clip(all0)
__device__ float g_ps[NB*NSEM*NCELL];                      // clip(agent_sem/5) [b][c][y*100+x]
__device__ float g_params[NB*4];                           // cos, sin, dx, dy per batch
__device__ float g_fcal;                                   // focal length (f32 of double computation)

// ---------- zero voxel scratch + compute focal constant ----------
__global__ void zero_kernel() {
    int t = blockIdx.x*blockDim.x + threadIdx.x;
    if (t == 0) {
        g_fcal = (float)(320.0 / tan(39.5 * 3.14159265358979323846 / 180.0));
    }
    float4 z = make_float4(0.f,0.f,0.f,0.f);
    const int n0 = NB*G0_PER_B/4;       // 800000
    const int n1 = NB*GS_PER_B*16/4;    // 1920000
    if (t < n0) ((float4*)g_g0)[t] = z;
    if (t < n1) ((float4*)g_gs)[t] = z;
}

// ---------- trilinear splat ----------
__global__ void splat_kernel(const float* __restrict__ obs, const float* __restrict__ sh) {
    int t = blockIdx.x*blockDim.x + threadIdx.x;
    if (t >= NB*NPIX) return;
    int b   = t / NPIX;
    int pix = t - b*NPIX;
    int i   = pix / FW;
    int j   = pix - i*FW;

    const float* obs_b = obs + (size_t)b*C_OBS*NPIX;
    float depth = obs_b[3*NPIX + pix];

    float4 s4 = ((const float4*)sh)[(size_t)b*NPIX + pix];
    float shm = (s4.x + s4.y + s4.z + s4.w) * 0.25f;
    float sfac = 1.0f + shm;

    float fc = g_fcal;
    float X = ((float)j - 319.5f) * depth / fc;
    float Z = (239.5f - (float)i) * depth / fc;      // gz = 479 - i  ->  gz - 239.5

    float xn = ((X + 250.0f)/5.0f - 50.0f)/100.0f*2.0f;
    float yn = (depth/5.0f - 50.0f)/100.0f*2.0f;
    float zn = ((Z + 88.0f)/5.0f - 32.0f)/80.0f*2.0f;
    xn = fminf(fmaxf(xn, -1.0f), 1.0f);
    yn = fminf(fmaxf(yn, -1.0f), 1.0f);
    zn = fminf(fmaxf(zn, -1.0f), 1.0f);

    float posx = xn*100.0f/2.0f + 50.0f;
    float posy = yn*100.0f/2.0f + 50.0f;
    float posz = zn*80.0f/2.0f + 40.0f;

    float fx = floorf(posx), fy = floorf(posy), fz = floorf(posz);
    float wx[2], wy[2], wz[2];
    int   px_[2], py_[2], pz_[2];
    #pragma unroll
    for (int k = 0; k < 2; k++) {
        float p;
        p = fx + (float)k; { bool s = (p > 0.0f && p < 100.0f); wx[k] = s ? (1.0f - fabsf(posx - p)) : 0.0f; px_[k] = (int)p; }
        p = fy + (float)k; { bool s = (p > 0.0f && p < 100.0f); wy[k] = s ? (1.0f - fabsf(posy - p)) : 0.0f; py_[k] = (int)p; }
        p = fz + (float)k; { bool s = (p > 0.0f && p <  80.0f); wz[k] = s ? (1.0f - fabsf(posz - p)) : 0.0f; pz_[k] = (int)p; }
    }
    if ((wx[0]==0.0f && wx[1]==0.0f) || (wy[0]==0.0f && wy[1]==0.0f) || (wz[0]==0.0f && wz[1]==0.0f))
        return;

    float* g0b = g_g0 + (size_t)b*G0_PER_B;
    float* gsb = g_gs + (size_t)b*GS_PER_B*16;

    float semv[16];
    bool semLoaded = false;

    #pragma unroll
    for (int kx = 0; kx < 2; kx++) {
        if (wx[kx] == 0.0f) continue;
        #pragma unroll
        for (int ky = 0; ky < 2; ky++) {
            float wxy = wx[kx]*wy[ky];
            if (wxy == 0.0f) continue;
            int cellxy = px_[kx]*100 + py_[ky];
            #pragma unroll
            for (int kz = 0; kz < 2; kz++) {
                float w = wxy*wz[kz];
                if (w == 0.0f) continue;
                int pz = pz_[kz];
                atomicAdd(&g0b[cellxy*80 + pz], sfac*w);
                if (pz >= AG_Z0 && pz < AG_Z0 + AG_NZ) {
                    if (!semLoaded) {
                        #pragma unroll
                        for (int c = 0; c < 16; c++)
                            semv[c] = obs_b[(4+c)*NPIX + pix] * sfac;
                        semLoaded = true;
                    }
                    float* dst = gsb + ((size_t)cellxy*AG_NZ + (pz - AG_Z0))*16;
                    atomicAdd((float4*)(dst+ 0), make_float4(semv[ 0]*w, semv[ 1]*w, semv[ 2]*w, semv[ 3]*w));
                    atomicAdd((float4*)(dst+ 4), make_float4(semv[ 4]*w, semv[ 5]*w, semv[ 6]*w, semv[ 7]*w));
                    atomicAdd((float4*)(dst+ 8), make_float4(semv[ 8]*w, semv[ 9]*w, semv[10]*w, semv[11]*w));
                    atomicAdd((float4*)(dst+12), make_float4(semv[12]*w, semv[13]*w, semv[14]*w, semv[15]*w));
                }
            }
        }
    }
}

// ---------- round + z-projection + clip ----------
__global__ void proj_kernel(float* __restrict__ dout) {
    int t = blockIdx.x*blockDim.x + threadIdx.x;
    if (t >= NB*NCELL) return;
    int b    = t / NCELL;
    int cell = t - b*NCELL;       // y*100 + x (output layout)
    int y = cell / 100, x = cell - y*100;
    int cxy = x*100 + y;          // grid layout

    const float4* g0p = (const float4*)(g_g0 + (size_t)b*G0_PER_B + (size_t)cxy*80);
    float acc_all = 0.0f, acc_ag = 0.0f;
    #pragma unroll
    for (int q = 0; q < 20; q++) {
        float4 v = g0p[q];
        float r0 = rintf(v.x), r1 = rintf(v.y), r2 = rintf(v.z), r3 = rintf(v.w);
        acc_all += r0 + r1 + r2 + r3;
        int z = q*4;
        if (z+0 >= 13 && z+0 < 25) acc_ag += r0;
        if (z+1 >= 13 && z+1 < 25) acc_ag += r1;
        if (z+2 >= 13 && z+2 < 25) acc_ag += r2;
        if (z+3 >= 13 && z+3 < 25) acc_ag += r3;
    }

    const float4* gsp = (const float4*)(g_gs + ((size_t)b*GS_PER_B + (size_t)cxy*AG_NZ)*16);
    float acc[16];
    #pragma unroll
    for (int c = 0; c < 16; c++) acc[c] = 0.0f;
    #pragma unroll
    for (int zz = 0; zz < AG_NZ; zz++) {
        #pragma unroll
        for (int q = 0; q < 4; q++) {
            float4 v = gsp[zz*4 + q];
            acc[q*4+0] += rintf(v.x);
            acc[q*4+1] += rintf(v.y);
            acc[q*4+2] += rintf(v.z);
            acc[q*4+3] += rintf(v.w);
        }
    }

    float pm = fminf(fmaxf(acc_ag / 1.0f, 0.0f), 1.0f);
    float pe = fminf(fmaxf(acc_all / 1.0f, 0.0f), 1.0f);
    g_pm0[t] = pm;
    g_pe0[t] = pe;
    dout[(size_t)b*NCELL + cell] = pm;   // fp_map_pred output
    #pragma unroll
    for (int c = 0; c < 16; c++)
        g_ps[((size_t)b*NSEM + c)*NCELL + cell] = fminf(fmaxf(acc[c] / 5.0f, 0.0f), 1.0f);
}

// ---------- pose update + sampling params ----------
__global__ void pose_kernel(const float* __restrict__ pose_obs,
                            const float* __restrict__ poses_last,
                            float* __restrict__ dout) {
    int b = threadIdx.x;
    if (b >= NB) return;
    const float DEGf = (float)57.29577951308232;
    float pl0 = poses_last[b*3+0], pl1 = poses_last[b*3+1], pl2 = poses_last[b*3+2];
    float po0 = pose_obs[b*3+0],  po1 = pose_obs[b*3+1],  po2 = pose_obs[b*3+2];
    float t0 = pl2 / DEGf;
    float s0 = sinf(t0), c0 = cosf(t0);
    float y_new = pl1 + po0*s0 + po1*c0;
    float x_new = pl0 + po0*c0 - po1*s0;
    float t_new = pl2 + po2*DEGf;
    t_new = fmodf(t_new - 180.0f, 360.0f) + 180.0f;
    t_new = fmodf(t_new + 180.0f, 360.0f) - 180.0f;

    dout[OUT_POSE_OFF      + b*3+0] = x_new;
    dout[OUT_POSE_OFF      + b*3+1] = y_new;
    dout[OUT_POSE_OFF      + b*3+2] = t_new;
    dout[OUT_POSE_OFF + 12 + b*3+0] = x_new;
    dout[OUT_POSE_OFF + 12 + b*3+1] = y_new;
    dout[OUT_POSE_OFF + 12 + b*3+2] = t_new;

    float stx = -(x_new*100.0f/5.0f - 240.0f)/240.0f;
    float sty = -(y_new*100.0f/5.0f - 240.0f)/240.0f;
    float stt = (90.0f - t_new) * (float)0.017453292519943295;
    g_params[b*4+0] = cosf(stt);
    g_params[b*4+1] = sinf(stt);
    g_params[b*4+2] = stx * 239.5f;   // dx = st_x*(W-1)/2
    g_params[b*4+3] = sty * 239.5f;   // dy
}

// ---------- fused rotate + translate grid_sample + max with maps_last ----------
__global__ void map_kernel(const float* __restrict__ maps_last, float* __restrict__ dout) {
    int t = blockIdx.x*blockDim.x + threadIdx.x;
    if (t >= NB*MC*MC) return;
    int b   = t / (MC*MC);
    int rem = t - b*(MC*MC);
    int i = rem / MC, j = rem - i*MC;

    float ct = g_params[b*4+0], st = g_params[b*4+1];
    float dx = g_params[b*4+2], dy = g_params[b*4+3];

    // translation sample position (pure shift)
    float xs = (float)j + dx, ys = (float)i + dy;
    float x0f = floorf(xs), y0f = floorf(ys);
    float wxa = (x0f + 1.0f) - xs, wxb = xs - x0f;
    float wya = (y0f + 1.0f) - ys, wyb = ys - y0f;
    float tw[4] = { wxa*wya, wxb*wya, wxa*wyb, wxb*wyb };
    int ix0 = (int)x0f, iy0 = (int)y0f;
    int txs[4] = { ix0, ix0+1, ix0, ix0+1 };
    int tys[4] = { iy0, iy0,   iy0+1, iy0+1 };

    int   nt = 0;
    int   lidx[16];
    float lw[16];
    #pragma unroll
    for (int k = 0; k < 4; k++) {
        int tx = txs[k], ty = tys[k];
        if (tx < 0 || tx >= MC || ty < 0 || ty >= MC) continue;
        // rotation sample at integer pixel (ty, tx)
        float gxr = -1.0f + (float)tx * (2.0f/479.0f);
        float gyr = -1.0f + (float)ty * (2.0f/479.0f);
        float xr = ((ct*gxr - st*gyr) + 1.0f) * 479.0f / 2.0f;
        float yr = ((st*gxr + ct*gyr) + 1.0f) * 479.0f / 2.0f;
        float rx0f = floorf(xr), ry0f = floorf(yr);
        float ra = (rx0f + 1.0f) - xr, rb = xr - rx0f;
        float rc = (ry0f + 1.0f) - yr, rd = yr - ry0f;
        float rw[4] = { ra*rc, rb*rc, ra*rd, rb*rd };
        int rx0 = (int)rx0f, ry0 = (int)ry0f;
        int rxs[4] = { rx0, rx0+1, rx0, rx0+1 };
        int rys[4] = { ry0, ry0,   ry0+1, ry0+1 };
        float twk = tw[k];
        #pragma unroll
        for (int s = 0; s < 4; s++) {
            int ix = rxs[s], iy = rys[s];
            // av nonzero only inside [240,340)x[190,290)
            if (ix >= 190 && ix < 290 && iy >= 240 && iy < 340) {
                lidx[nt] = (iy - 240)*100 + (ix - 190);
                lw[nt]   = twk * rw[s];
                nt++;
            }
        }
    }

    size_t base = (size_t)b*C_OBS*MC*MC + (size_t)i*MC + j;
    const float* mlp  = maps_last + base;
    float*       outp = dout + OUT_MAP_OFF + base;

    if (nt == 0) {   // fast path: translated == 0 everywhere
        #pragma unroll
        for (int c = 0; c < C_OBS; c++)
            outp[(size_t)c*MC*MC] = fmaxf(mlp[(size_t)c*MC*MC], 0.0f);
        return;
    }

    #pragma unroll
    for (int c = 0; c < C_OBS; c++) {
        float tv = 0.0f;
        if (c != 2 && c != 3) {
            const float* src;
            if      (c == 0) src = g_pm0 + (size_t)b*NCELL;
            else if (c == 1) src = g_pe0 + (size_t)b*NCELL;
            else             src = g_ps  + ((size_t)b*NSEM + (c-4))*NCELL;
            for (int k = 0; k < nt; k++)
                tv += lw[k] * src[lidx[k]];
        }
        outp[(size_t)c*MC*MC] = fmaxf(mlp[(size_t)c*MC*MC], tv);
    }
}

extern "C" void kernel_launch(void* const* d_in, const int* in_sizes, int n_in,
                              void* d_out, int out_size) {
    const float* obs        = (const float*)d_in[0];
    const float* pose_obs   = (const float*)d_in[1];
    const float* maps_last  = (const float*)d_in[2];
    const float* poses_last = (const float*)d_in[3];
    const float* sh         = (const float*)d_in[4];
    float* out = (float*)d_out;

    zero_kernel<<<(NB*GS_PER_B*16/4 + 255)/256, 256>>>();
    pose_kernel<<<1, 32>>>(pose_obs, poses_last, out);
    splat_kernel<<<NB*NPIX/256, 256>>>(obs, sh);
    proj_kernel<<<(NB*NCELL + 255)/256, 256>>>(out);
    map_kernel<<<NB*MC*MC/256, 256>>>(maps_last, out);
}